// round 16
// baseline (speedup 1.0000x reference)
#include <cuda_runtime.h>
#include <cuda_fp16.h>
#include <cstdint>
#include <math.h>

// Problem constants
#define B_DIM 8
#define C_DIM 256
#define S_DIM 8192
#define N_PTS 65536
#define N_CODES 1024
#define Z_ELEMS 16777216
#define BATCH_STRIDE 2097152

// Output layout (concatenated, fp32)
#define ZQ_OFF 0
#define IDX_OFF 16777216
#define LOSS_OFF 16842752
#define PERP_OFF 16842753

#define ZPAD 132                          // half2 per smem k2 row (128 + 4 pad)
#define VROW 136                          // halves per vtile row
#define GEMM_SMEM (3*128*ZPAD*4)          // Zs + Es0 + Es1 = 202752 B
#define EXACT_SMEM (256*64*4)             // fp32 [k][m] tile (frozen layout)
#define SCAP 4096                         // candidates per 64-pt group

typedef unsigned long long ull;

// Scratch (device globals; runtime allocation forbidden)
__device__ float    g_e2[N_CODES];        // ||e_j||^2 (FROZEN chain)
__device__ float    g_cnt[N_CODES];
__device__ double   g_loss;
__device__ int      g_emax_bits = 0;      // max over codes of max|e| (float bits)
__device__ __half2  g_ehT[128 * N_CODES];         // e fp16 [k2 128][code 1024]
__device__ __half   g_v[(size_t)N_PTS * N_CODES]; // approx scores (128MB)
__device__ int      g_ccnt[1024];                 // per-group candidate counts
__device__ unsigned short g_cand[1024 * SCAP];    // per-group candidates (pl<<10|j)

__device__ __forceinline__ void cp16(unsigned saddr, const void* g) {
    asm volatile("cp.async.cg.shared.global [%0], [%1], 16;" :: "r"(saddr), "l"(g));
}
#define CP_COMMIT() asm volatile("cp.async.commit_group;")
#define CP_WAIT0()  asm volatile("cp.async.wait_group 0;")

// ---------------------------------------------------------------------------
// K1: per-code ||e||^2 (FROZEN chain), emax, zero accumulators.
// ---------------------------------------------------------------------------
__global__ void vq_prep_e(const float* __restrict__ embed) {
    int t = threadIdx.x, lane = t & 31;
    int code = blockIdx.x * 8 + (t >> 5);
    const float* row = embed + code * C_DIM;

    float s = 0.f;                         // FROZEN ||e||^2 chain
#pragma unroll
    for (int q = 0; q < 8; ++q) { float e = row[lane + q * 32]; s = fmaf(e, e, s); }
#pragma unroll
    for (int off = 16; off > 0; off >>= 1) s += __shfl_down_sync(0xffffffffu, s, off);
    if (lane == 0) g_e2[code] = s;

    float mx = 0.f;
#pragma unroll
    for (int q = 0; q < 8; ++q) mx = fmaxf(mx, fabsf(row[lane + q * 32]));
#pragma unroll
    for (int off = 16; off > 0; off >>= 1)
        mx = fmaxf(mx, __shfl_down_sync(0xffffffffu, mx, off));
    if (lane == 0) atomicMax(&g_emax_bits, __float_as_int(mx));

    if (blockIdx.x == 0) {
        for (int i = t; i < N_CODES; i += 256) { g_cnt[i] = 0.f; g_ccnt[i] = 0; }
        if (t == 0) g_loss = 0.0;
    }
}

// ---------------------------------------------------------------------------
// K1b: e -> transposed half2 [k2][code]. grid 128 x 256.
// ---------------------------------------------------------------------------
__global__ void vq_transpose_e(const float* __restrict__ embed) {
    int k2 = blockIdx.x;
    for (int c = threadIdx.x; c < N_CODES; c += 256) {
        float lo = __ldg(embed + (size_t)c * C_DIM + 2 * k2);
        float hi = __ldg(embed + (size_t)c * C_DIM + 2 * k2 + 1);
        g_ehT[k2 * N_CODES + c] = __floats2half2_rn(lo, hi);
    }
}

// ---------------------------------------------------------------------------
// K2: resident scoring GEMM: one block = 128 pts x ALL 1024 codes.
// fp32 z loaded directly (contiguous rows), converted in-kernel.
// E chunks (128 codes) cp.async double-buffered. Per-chunk: quad-microtile
// HFMA2 compute (R15-validated numerics), smem-staged coalesced dump.
// After 8 chunks: local per-point fp32 min -> tau -> threshold scan of own
// (L2-hot) scores -> candidate lists.  grid 512, 256 threads.
// ---------------------------------------------------------------------------
__global__ void __launch_bounds__(256, 1)
vq_gemm_all(const float* __restrict__ z) {
    extern __shared__ __half2 sh2[];
    __half2* Zs = sh2;                     // [k2 128][ZPAD]
    __half2* Eb[2] = { sh2 + 128 * ZPAD, sh2 + 2 * 128 * ZPAD };
    __shared__ float sred[128 * 16];
    __shared__ float pmin[128];
    __shared__ float Usm[128];

    const int t  = threadIdx.x;
    const int tx = t & 15;
    const int ty = t >> 4;
    const int tile = blockIdx.x;           // 0..511
    const int pbase = tile * 128;
    const int b  = tile >> 6;
    const int s0 = (tile & 63) * 128;
    const float* zb = z + (size_t)b * BATCH_STRIDE + s0;

    // Prefetch E chunk 0 (overlaps the z load below).
    {
        unsigned sb = (unsigned)__cvta_generic_to_shared(Eb[0]);
#pragma unroll
        for (int i = 0; i < 16; ++i) {
            int lin = i * 256 + t, k2 = lin >> 5, seg = lin & 31;
            cp16(sb + (unsigned)(k2 * ZPAD + seg * 4) * 4,
                 g_ehT + (size_t)k2 * N_CODES + seg * 4);
        }
        CP_COMMIT();
    }

    // Load z fp32 (coalesced 512B rows), convert to half2 [k2][pt].
#pragma unroll
    for (int i = 0; i < 16; ++i) {
        int lin = i * 256 + t, k2 = lin >> 5, q = lin & 31;
        float4 v0 = *(const float4*)(zb + (size_t)(2 * k2) * S_DIM + q * 4);
        float4 v1 = *(const float4*)(zb + (size_t)(2 * k2 + 1) * S_DIM + q * 4);
        __half2 h[4];
        h[0] = __floats2half2_rn(v0.x, v1.x);
        h[1] = __floats2half2_rn(v0.y, v1.y);
        h[2] = __floats2half2_rn(v0.z, v1.z);
        h[3] = __floats2half2_rn(v0.w, v1.w);
        *(uint4*)(Zs + k2 * ZPAD + q * 4) = *(uint4*)h;
    }
    __syncthreads();

    // Per-point U = sum|z| (bound input; fp16-rounded values, covered by slack).
    if (t < 128) {
        float u = 0.f;
#pragma unroll 8
        for (int k2 = 0; k2 < 128; ++k2) {
            float2 f = __half22float2(Zs[k2 * ZPAD + t]);
            u += fabsf(f.x) + fabsf(f.y);
        }
        Usm[t] = u;
        pmin[t] = INFINITY;
    }
    CP_WAIT0();
    __syncthreads();

    for (int c = 0; c < 8; ++c) {
        if (c > 0) { CP_WAIT0(); __syncthreads(); }
        if (c < 7) {
            unsigned sb = (unsigned)__cvta_generic_to_shared(Eb[(c + 1) & 1]);
            const __half2* src = g_ehT + (size_t)(c + 1) * 128;
#pragma unroll
            for (int i = 0; i < 16; ++i) {
                int lin = i * 256 + t, k2 = lin >> 5, seg = lin & 31;
                cp16(sb + (unsigned)(k2 * ZPAD + seg * 4) * 4,
                     src + (size_t)k2 * N_CODES + seg * 4);
            }
            CP_COMMIT();
        }
        const __half2* Es = Eb[c & 1];
        const int cbase = c * 128;

        // ---- compute (R15-validated) ----
        float macc[2][4][2][4];
#pragma unroll
        for (int pg = 0; pg < 2; ++pg)
#pragma unroll
            for (int i = 0; i < 4; ++i)
#pragma unroll
                for (int cg = 0; cg < 2; ++cg)
#pragma unroll
                    for (int cc = 0; cc < 4; ++cc) macc[pg][i][cg][cc] = 0.f;

        const __half2 zero2 = __float2half2_rn(0.f);
#pragma unroll
        for (int qtr = 0; qtr < 4; ++qtr) {
            __half2 hacc[2][4][2][4];
#pragma unroll
            for (int pg = 0; pg < 2; ++pg)
#pragma unroll
                for (int i = 0; i < 4; ++i)
#pragma unroll
                    for (int cg = 0; cg < 2; ++cg)
#pragma unroll
                        for (int cc = 0; cc < 4; ++cc) hacc[pg][i][cg][cc] = zero2;

            for (int k2 = qtr * 32; k2 < qtr * 32 + 32; ++k2) {
                __half2 a[2][4], e[2][4];
                *(uint4*)&a[0][0] = *(const uint4*)(Zs + k2 * ZPAD + tx * 4);
                *(uint4*)&a[1][0] = *(const uint4*)(Zs + k2 * ZPAD + 64 + tx * 4);
                *(uint4*)&e[0][0] = *(const uint4*)(Es + k2 * ZPAD + ty * 4);
                *(uint4*)&e[1][0] = *(const uint4*)(Es + k2 * ZPAD + 64 + ty * 4);
#pragma unroll
                for (int pg = 0; pg < 2; ++pg)
#pragma unroll
                    for (int i = 0; i < 4; ++i)
#pragma unroll
                        for (int cg = 0; cg < 2; ++cg)
#pragma unroll
                            for (int cc = 0; cc < 4; ++cc)
                                hacc[pg][i][cg][cc] =
                                    __hfma2(a[pg][i], e[cg][cc], hacc[pg][i][cg][cc]);
            }
#pragma unroll
            for (int pg = 0; pg < 2; ++pg)
#pragma unroll
                for (int i = 0; i < 4; ++i)
#pragma unroll
                    for (int cg = 0; cg < 2; ++cg)
#pragma unroll
                        for (int cc = 0; cc < 4; ++cc) {
                            float2 f = __half22float2(hacc[pg][i][cg][cc]);
                            macc[pg][i][cg][cc] += f.x + f.y;
                        }
        }
        __syncthreads();                   // done reading Eb[c&1]

        // ---- epilogue: stage vtile in consumed buffer, per-pt min ----
        __half* vtile = (__half*)Eb[c & 1];
        float Bv[2][4];
#pragma unroll
        for (int cg = 0; cg < 2; ++cg)
#pragma unroll
            for (int cc = 0; cc < 4; ++cc)
                Bv[cg][cc] = __ldg(&g_e2[cbase + cg * 64 + ty * 4 + cc]);

#pragma unroll
        for (int pg = 0; pg < 2; ++pg)
#pragma unroll
            for (int i = 0; i < 4; ++i) {
                int pl = pg * 64 + tx * 4 + i;
                float vmn = INFINITY;
#pragma unroll
                for (int cg = 0; cg < 2; ++cg) {
                    float v0 = fmaf(-2.f, macc[pg][i][cg][0], Bv[cg][0]);
                    float v1 = fmaf(-2.f, macc[pg][i][cg][1], Bv[cg][1]);
                    float v2 = fmaf(-2.f, macc[pg][i][cg][2], Bv[cg][2]);
                    float v3 = fmaf(-2.f, macc[pg][i][cg][3], Bv[cg][3]);
                    vmn = fminf(vmn, fminf(fminf(v0, v1), fminf(v2, v3)));
                    __half2 h01 = __floats2half2_rn(v0, v1);
                    __half2 h23 = __floats2half2_rn(v2, v3);
                    uint2 w;
                    w.x = *(unsigned*)&h01;
                    w.y = *(unsigned*)&h23;
                    *(uint2*)(vtile + pl * VROW + cg * 64 + ty * 4) = w;
                }
                sred[pl * 16 + ty] = vmn;
            }
        __syncthreads();

        if (t < 128) {
            float m = sred[t * 16];
#pragma unroll
            for (int y = 1; y < 16; ++y) m = fminf(m, sred[t * 16 + y]);
            pmin[t] = fminf(pmin[t], m);
        }
        // coalesced dump: 128 rows x 256B
#pragma unroll
        for (int i = 0; i < 8; ++i) {
            int lin = i * 256 + t, row = lin >> 4, qq = lin & 15;
            *(uint4*)(g_v + (size_t)(pbase + row) * N_CODES + cbase + qq * 8) =
                *(uint4*)(vtile + row * VROW + qq * 8);
        }
    }
    __syncthreads();

    // ---- threshold scan of own scores (L2-hot). warp w -> rows w,w+8,... ----
    const float emax = __int_as_float(g_emax_bits);
    const int w = t >> 5, l = t & 31;
    for (int r = w; r < 128; r += 8) {
        const int p = pbase + r;
        // sound tau (validated R14/R15): 2*eps <= 0.045*U*emax; 1.2e-3 slack
        // covers fp16 dump rounding of candidates + reference fl32 skew.
        const float tau = pmin[r] + fmaf(Usm[r] * emax, 0.045f, 1.2e-3f);
        const int grp = p >> 6, pl = p & 63;
        const uint4* vp = (const uint4*)(g_v + (size_t)p * N_CODES);
#pragma unroll
        for (int i = 0; i < 4; ++i) {
            uint4 u = __ldg(&vp[l + 32 * i]);
            __half2 h0 = *(__half2*)&u.x, h1 = *(__half2*)&u.y;
            __half2 h2 = *(__half2*)&u.z, h3 = *(__half2*)&u.w;
            __half2 m = __hmin2(__hmin2(h0, h1), __hmin2(h2, h3));
            float mn = fminf(__low2float(m), __high2float(m));
            if (mn <= tau) {
                float vf[8];
                vf[0] = __low2float(h0); vf[1] = __high2float(h0);
                vf[2] = __low2float(h1); vf[3] = __high2float(h1);
                vf[4] = __low2float(h2); vf[5] = __high2float(h2);
                vf[6] = __low2float(h3); vf[7] = __high2float(h3);
#pragma unroll
                for (int s = 0; s < 8; ++s) {
                    if (vf[s] <= tau) {
                        int j = (l + 32 * i) * 8 + s;
                        int base = atomicAdd(&g_ccnt[grp], 1);
                        if (base < SCAP)
                            g_cand[grp * SCAP + base] =
                                (unsigned short)((pl << 10) | j);
                    }
                }
            }
        }
    }
}

// ---------------------------------------------------------------------------
// K3: exact (FROZEN) recheck + fused quantize/loss/histogram. grid 1024.
// A recomputed in-kernel with the FROZEN chain.
// ---------------------------------------------------------------------------
__global__ void vq_exact_q(const float* __restrict__ z,
                           const float* __restrict__ embed,
                           float* __restrict__ out) {
    extern __shared__ float Ze[];          // [k 256][m 64] (frozen layout)
    __shared__ ull    key[64];
    __shared__ float  sA[64];
    __shared__ int    sidx[64];
    __shared__ double red[256];

    const int t  = threadIdx.x;
    const int tb = blockIdx.x;
    const int b  = tb >> 7;
    const int s0 = (tb & 127) * 64;
    const float* zb = z + (size_t)b * BATCH_STRIDE + s0;

#pragma unroll
    for (int i = 0; i < 16; ++i) {
        int lin = i * 256 + t;
        int k = lin >> 4, mq = lin & 15;
        *(float4*)(Ze + k * 64 + mq * 4) = *(const float4*)(zb + (size_t)k * S_DIM + mq * 4);
    }
    if (t < 64) key[t] = ~0ull;
    __syncthreads();

    if (t < 64) {                          // FROZEN A chain
        float a = 0.f;
#pragma unroll 8
        for (int k = 0; k < 256; ++k) {
            float v = Ze[k * 64 + t];
            a = fmaf(v, v, a);
        }
        sA[t] = a;
    }
    __syncthreads();

    const int ncand = g_ccnt[tb];
    if (ncand <= SCAP) {
        for (int i = t; i < ncand; i += 256) {
            int e  = g_cand[tb * SCAP + i];
            int pl = e >> 10, j = e & 1023;
            float m = 0.f;                 // FROZEN exact chain
            const float* er = embed + (size_t)j * C_DIM;
#pragma unroll 8
            for (int k = 0; k < 256; ++k)
                m = fmaf(Ze[k * 64 + pl], __ldg(er + k), m);
            float d = __fadd_rn(__fadd_rn(sA[pl], g_e2[j]), -2.0f * m);
            atomicMin(&key[pl], ((ull)(unsigned)__float_as_int(d) << 32) | (unsigned)j);
        }
    } else {                               // overflow: deterministic full eval
        for (int i = t; i < 64 * 1024; i += 256) {
            int pl = i >> 10, j = i & 1023;
            float m = 0.f;
            const float* er = embed + (size_t)j * C_DIM;
#pragma unroll 8
            for (int k = 0; k < 256; ++k)
                m = fmaf(Ze[k * 64 + pl], __ldg(er + k), m);
            float d = __fadd_rn(__fadd_rn(sA[pl], g_e2[j]), -2.0f * m);
            atomicMin(&key[pl], ((ull)(unsigned)__float_as_int(d) << 32) | (unsigned)j);
        }
    }
    __syncthreads();

    if (t < 64) {
        int bi = (int)(key[t] & 0xFFFFFFFFull);
        sidx[t] = bi;
        out[IDX_OFF + tb * 64 + t] = (float)bi;
        atomicAdd(&g_cnt[bi], 1.0f);
    }
    __syncthreads();

    // fused quantize (FROZEN arithmetic), z read from Ze
    float* qb = out + ZQ_OFF + (size_t)b * BATCH_STRIDE + s0;
    double lacc = 0.0;
#pragma unroll
    for (int i = 0; i < 16; ++i) {
        int lin = i * 256 + t;
        int c = lin >> 4, mq = lin & 15;
        float4 zv = *(const float4*)(Ze + c * 64 + mq * 4);
        float4 ev;
        ev.x = __ldg(embed + (size_t)sidx[mq * 4 + 0] * C_DIM + c);
        ev.y = __ldg(embed + (size_t)sidx[mq * 4 + 1] * C_DIM + c);
        ev.z = __ldg(embed + (size_t)sidx[mq * 4 + 2] * C_DIM + c);
        ev.w = __ldg(embed + (size_t)sidx[mq * 4 + 3] * C_DIM + c);
        float dx = __fadd_rn(ev.x, -zv.x);
        float dy = __fadd_rn(ev.y, -zv.y);
        float dz = __fadd_rn(ev.z, -zv.z);
        float dw = __fadd_rn(ev.w, -zv.w);
        float4 qv;
        qv.x = __fadd_rn(zv.x, dx);
        qv.y = __fadd_rn(zv.y, dy);
        qv.z = __fadd_rn(zv.z, dz);
        qv.w = __fadd_rn(zv.w, dw);
        *(float4*)(qb + (size_t)c * S_DIM + mq * 4) = qv;
        lacc += (double)(dx * dx) + (double)(dy * dy)
              + (double)(dz * dz) + (double)(dw * dw);
    }

    red[t] = lacc;
    __syncthreads();
    for (int off = 128; off > 0; off >>= 1) {
        if (t < off) red[t] += red[t + off];
        __syncthreads();
    }
    if (t == 0) atomicAdd(&g_loss, red[0]);
}

// ---------------------------------------------------------------------------
// K4: finalize loss + perplexity.
// ---------------------------------------------------------------------------
__global__ void vq_finalize_kernel(float* __restrict__ out) {
    __shared__ float sred[1024];
    int t = threadIdx.x;
    float p = g_cnt[t] * (1.0f / (float)N_PTS);
    sred[t] = p * logf(p + 1e-10f);
    __syncthreads();
    for (int off = 512; off > 0; off >>= 1) {
        if (t < off) sred[t] += sred[t + off];
        __syncthreads();
    }
    if (t == 0) {
        out[PERP_OFF] = expf(-sred[0]);
        out[LOSS_OFF] = 0.25f * (float)(g_loss / (double)Z_ELEMS);
    }
}

// ---------------------------------------------------------------------------
extern "C" void kernel_launch(void* const* d_in, const int* in_sizes, int n_in,
                              void* d_out, int out_size) {
    const float* z     = (const float*)d_in[0];
    const float* embed = (const float*)d_in[1];
    float* out = (float*)d_out;

    cudaFuncSetAttribute(vq_gemm_all, cudaFuncAttributeMaxDynamicSharedMemorySize, GEMM_SMEM);
    cudaFuncSetAttribute(vq_exact_q,  cudaFuncAttributeMaxDynamicSharedMemorySize, EXACT_SMEM);

    vq_prep_e<<<128, 256>>>(embed);
    vq_transpose_e<<<128, 256>>>(embed);
    vq_gemm_all<<<512, 256, GEMM_SMEM>>>(z);
    vq_exact_q<<<1024, 256, EXACT_SMEM>>>(z, embed, out);
    vq_finalize_kernel<<<1, 1024>>>(out);
}

// round 17
// speedup vs baseline: 1.3988x; 1.3988x over previous
#include <cuda_runtime.h>
#include <cuda_fp16.h>
#include <cstdint>
#include <math.h>

// Problem constants
#define B_DIM 8
#define C_DIM 256
#define S_DIM 8192
#define N_PTS 65536
#define N_CODES 1024
#define Z_ELEMS 16777216
#define BATCH_STRIDE 2097152

// Output layout (concatenated, fp32)
#define ZQ_OFF 0
#define IDX_OFF 16777216
#define LOSS_OFF 16842752
#define PERP_OFF 16842753

#define ZPAD 132                          // half2 per smem z k2-row (128 + 4 pad)
#define EPAD 68                           // half2 per smem e k2-row (64 + 4 pad)
#define VROW 72                           // halves per vtile row (144B, 16B-mult)
#define GEMM_SMEM ((128*ZPAD + 128*EPAD)*4)   // 102400 B -> 2 CTAs/SM
#define PREPZ_SMEM (256*68*4)             // padded fp32 [k][m] tile
#define ZTS 257                           // floats per Zt row (conflict-free)
#define EXACT_SMEM (64*ZTS*4)             // 65792 B
#define SCAP 4096                         // candidates per 64-pt group

typedef unsigned long long ull;

// Scratch (device globals; runtime allocation forbidden)
__device__ float    g_e2[N_CODES];        // ||e_j||^2 (FROZEN chain)
__device__ float    g_A[N_PTS];           // sum z^2 (FROZEN chain)
__device__ float    g_U[N_PTS];           // sum |z|
__device__ float    g_cnt[N_CODES];
__device__ double   g_loss;
__device__ int      g_emax_bits = 0;      // max over codes of max|e| (float bits)
__device__ unsigned g_vmin[N_PTS];        // per-point min score, monotonic-encoded
__device__ __half2  g_zhT[(size_t)N_PTS * 128];   // z fp16 [tile512][k2 128][pt 128]
__device__ __half2  g_ehT[128 * N_CODES];         // e fp16 [k2 128][code 1024]
__device__ __half   g_v[(size_t)N_PTS * N_CODES]; // approx scores (128MB)
__device__ int      g_ccnt[1024];                 // per-group candidate counts
__device__ unsigned short g_cand[1024 * SCAP];    // per-group candidates (pl<<10|j)

// monotonic float<->unsigned order encoding
__device__ __forceinline__ unsigned enc_f(float v) {
    unsigned b = __float_as_uint(v);
    return b ^ ((unsigned)(((int)b) >> 31) | 0x80000000u);
}
__device__ __forceinline__ float dec_f(unsigned e) {
    unsigned b = (e & 0x80000000u) ? (e ^ 0x80000000u) : ~e;
    return __uint_as_float(b);
}

// ---------------------------------------------------------------------------
// K1: per-code ||e||^2 (FROZEN chain), emax, zero accumulators.
// ---------------------------------------------------------------------------
__global__ void vq_prep_e(const float* __restrict__ embed) {
    int t = threadIdx.x, lane = t & 31;
    int code = blockIdx.x * 8 + (t >> 5);
    const float* row = embed + code * C_DIM;

    float s = 0.f;                         // FROZEN ||e||^2 chain
#pragma unroll
    for (int q = 0; q < 8; ++q) { float e = row[lane + q * 32]; s = fmaf(e, e, s); }
#pragma unroll
    for (int off = 16; off > 0; off >>= 1) s += __shfl_down_sync(0xffffffffu, s, off);
    if (lane == 0) g_e2[code] = s;

    float mx = 0.f;
#pragma unroll
    for (int q = 0; q < 8; ++q) mx = fmaxf(mx, fabsf(row[lane + q * 32]));
#pragma unroll
    for (int off = 16; off > 0; off >>= 1)
        mx = fmaxf(mx, __shfl_down_sync(0xffffffffu, mx, off));
    if (lane == 0) atomicMax(&g_emax_bits, __float_as_int(mx));

    if (blockIdx.x == 0) {
        for (int i = t; i < N_CODES; i += 256) { g_cnt[i] = 0.f; g_ccnt[i] = 0; }
        if (t == 0) g_loss = 0.0;
    }
}

// ---------------------------------------------------------------------------
// K1b: e -> transposed half2 [k2][code]. grid 128 x 256.
// ---------------------------------------------------------------------------
__global__ void vq_transpose_e(const float* __restrict__ embed) {
    int k2 = blockIdx.x;
    for (int c = threadIdx.x; c < N_CODES; c += 256) {
        float lo = __ldg(embed + (size_t)c * C_DIM + 2 * k2);
        float hi = __ldg(embed + (size_t)c * C_DIM + 2 * k2 + 1);
        g_ehT[k2 * N_CODES + c] = __floats2half2_rn(lo, hi);
    }
}

// ---------------------------------------------------------------------------
// K2: per-point A (FROZEN), U, vmin init, transposed half2 z. 64 pts/block.
// ---------------------------------------------------------------------------
__global__ void vq_prep_z(const float* __restrict__ z) {
    extern __shared__ float Ze[];          // [k 256][stride 68]
    const int t  = threadIdx.x;
    const int tb = blockIdx.x;
    const int b  = tb >> 7;
    const int s0 = (tb & 127) * 64;
    const float* zb = z + (size_t)b * BATCH_STRIDE + s0;

#pragma unroll
    for (int i = 0; i < 16; ++i) {
        int lin = i * 256 + t;
        int k = lin >> 4, mq = lin & 15;
        *(float4*)(Ze + k * 68 + mq * 4) = *(const float4*)(zb + (size_t)k * S_DIM + mq * 4);
    }
    __syncthreads();

    if (t < 64) {
        float a = 0.f, u = 0.f;
#pragma unroll 8
        for (int k = 0; k < 256; ++k) {
            float v = Ze[k * 68 + t];
            a = fmaf(v, v, a);              // FROZEN A chain
            u += fabsf(v);
        }
        int p = tb * 64 + t;
        g_A[p] = a;
        g_U[p] = u;
        g_vmin[p] = 0xFFFFFFFFu;
    }

    // transposed half2 write: 128 k2 x 64 pts, coalesced
    const int tile = tb >> 1, moff = (tb & 1) * 64;
#pragma unroll
    for (int i = 0; i < 32; ++i) {
        int lin = i * 256 + t;
        int k2 = lin >> 6, pl = lin & 63;
        g_zhT[(size_t)tile * 16384 + k2 * 128 + moff + pl] =
            __floats2half2_rn(Ze[(2 * k2) * 68 + pl], Ze[(2 * k2 + 1) * 68 + pl]);
    }
}

// ---------------------------------------------------------------------------
// K3: fp16 HFMA2 scoring GEMM. grid (512 pt-tiles, 16 code-tiles), 256 thr.
// 64-code tiles -> 100KB smem -> 2 CTAs/SM. Microtile 8 pts x 4 codes.
// Per-(pt,code) chain identical to R15 (4 qtrs of 32 sequential hfma2 + fp32).
// ---------------------------------------------------------------------------
__global__ void __launch_bounds__(256, 2)
vq_gemm_h() {
    extern __shared__ __half2 sh2[];
    __half2* Zs = sh2;                     // [k2 128][ZPAD]
    __half2* Es = sh2 + 128 * ZPAD;        // [k2 128][EPAD]

    const int t  = threadIdx.x;
    const int tx = t & 15;
    const int ty = t >> 4;
    const int pbase = blockIdx.x * 128;
    const int cbase = blockIdx.y * 64;

    const __half2* gz = g_zhT + (size_t)blockIdx.x * 16384;
#pragma unroll
    for (int i = 0; i < 16; ++i) {
        int lin = i * 256 + t, k2 = lin >> 5, q = lin & 31;
        *(uint4*)(Zs + k2 * ZPAD + q * 4) = *(const uint4*)(gz + k2 * 128 + q * 4);
    }
#pragma unroll
    for (int i = 0; i < 8; ++i) {
        int lin = i * 256 + t, k2 = lin >> 4, q = lin & 15;
        *(uint4*)(Es + k2 * EPAD + q * 4) =
            *(const uint4*)(g_ehT + (size_t)k2 * N_CODES + cbase + q * 4);
    }
    __syncthreads();

    float macc[2][4][4];
#pragma unroll
    for (int pg = 0; pg < 2; ++pg)
#pragma unroll
        for (int i = 0; i < 4; ++i)
#pragma unroll
            for (int cc = 0; cc < 4; ++cc) macc[pg][i][cc] = 0.f;

    const __half2 zero2 = __float2half2_rn(0.f);
#pragma unroll
    for (int qtr = 0; qtr < 4; ++qtr) {
        __half2 hacc[2][4][4];
#pragma unroll
        for (int pg = 0; pg < 2; ++pg)
#pragma unroll
            for (int i = 0; i < 4; ++i)
#pragma unroll
                for (int cc = 0; cc < 4; ++cc) hacc[pg][i][cc] = zero2;

        for (int k2 = qtr * 32; k2 < qtr * 32 + 32; ++k2) {
            __half2 a[2][4], e[4];
            *(uint4*)&a[0][0] = *(const uint4*)(Zs + k2 * ZPAD + tx * 4);
            *(uint4*)&a[1][0] = *(const uint4*)(Zs + k2 * ZPAD + 64 + tx * 4);
            *(uint4*)&e[0]    = *(const uint4*)(Es + k2 * EPAD + ty * 4);
#pragma unroll
            for (int pg = 0; pg < 2; ++pg)
#pragma unroll
                for (int i = 0; i < 4; ++i)
#pragma unroll
                    for (int cc = 0; cc < 4; ++cc)
                        hacc[pg][i][cc] = __hfma2(a[pg][i], e[cc], hacc[pg][i][cc]);
        }
#pragma unroll
        for (int pg = 0; pg < 2; ++pg)
#pragma unroll
            for (int i = 0; i < 4; ++i)
#pragma unroll
                for (int cc = 0; cc < 4; ++cc) {
                    float2 f = __half22float2(hacc[pg][i][cc]);
                    macc[pg][i][cc] += f.x + f.y;
                }
    }
    __syncthreads();                       // done reading Zs/Es

    __half* vtile = (__half*)Es;           // [128][VROW]
    float*  sred  = (float*)Zs;            // [128][16]

    float Bv[4];
#pragma unroll
    for (int cc = 0; cc < 4; ++cc)
        Bv[cc] = __ldg(&g_e2[cbase + ty * 4 + cc]);

#pragma unroll
    for (int pg = 0; pg < 2; ++pg)
#pragma unroll
        for (int i = 0; i < 4; ++i) {
            int pl = pg * 64 + tx * 4 + i;
            float v0 = fmaf(-2.f, macc[pg][i][0], Bv[0]);
            float v1 = fmaf(-2.f, macc[pg][i][1], Bv[1]);
            float v2 = fmaf(-2.f, macc[pg][i][2], Bv[2]);
            float v3 = fmaf(-2.f, macc[pg][i][3], Bv[3]);
            float vmn = fminf(fminf(v0, v1), fminf(v2, v3));
            __half2 h01 = __floats2half2_rn(v0, v1);
            __half2 h23 = __floats2half2_rn(v2, v3);
            uint2 w;
            w.x = *(unsigned*)&h01;
            w.y = *(unsigned*)&h23;
            *(uint2*)(vtile + pl * VROW + ty * 4) = w;
            sred[pl * 16 + ty] = vmn;
        }
    __syncthreads();

    if (t < 128) {
        float m = sred[t * 16];
#pragma unroll
        for (int y = 1; y < 16; ++y) m = fminf(m, sred[t * 16 + y]);
        atomicMin(&g_vmin[pbase + t], enc_f(m));
    }
    // coalesced dump: 128 rows x 128B
#pragma unroll
    for (int i = 0; i < 4; ++i) {
        int lin = i * 256 + t, row = lin >> 3, qq = lin & 7;
        *(uint4*)(g_v + (size_t)(pbase + row) * N_CODES + cbase + qq * 8) =
            *(uint4*)(vtile + row * VROW + qq * 8);
    }
}

// ---------------------------------------------------------------------------
// K4: threshold scan, warp per point, fully coalesced. grid 8192 x 256.
// ---------------------------------------------------------------------------
__global__ void vq_scan() {
    const int t = threadIdx.x;
    const int w = t >> 5, l = t & 31;
    const int p = blockIdx.x * 8 + w;

    float gmin = dec_f(g_vmin[p]);
    // sound tau (validated R14/R15): 2*eps <= 0.045*U*emax; 1.2e-3 slack
    // covers fp16 dump rounding of candidates + reference fl32 skew.
    const float tau = gmin +
        fmaf(g_U[p] * __int_as_float(g_emax_bits), 0.045f, 1.2e-3f);

    const int grp = p >> 6, pl = p & 63;
    const uint4* vp = (const uint4*)(g_v + (size_t)p * N_CODES);
#pragma unroll
    for (int i = 0; i < 4; ++i) {
        uint4 u = __ldg(&vp[l + 32 * i]);
        __half2 h0 = *(__half2*)&u.x, h1 = *(__half2*)&u.y;
        __half2 h2 = *(__half2*)&u.z, h3 = *(__half2*)&u.w;
        __half2 m = __hmin2(__hmin2(h0, h1), __hmin2(h2, h3));
        float mn = fminf(__low2float(m), __high2float(m));
        if (mn <= tau) {
            float vf[8];
            vf[0] = __low2float(h0); vf[1] = __high2float(h0);
            vf[2] = __low2float(h1); vf[3] = __high2float(h1);
            vf[4] = __low2float(h2); vf[5] = __high2float(h2);
            vf[6] = __low2float(h3); vf[7] = __high2float(h3);
#pragma unroll
            for (int s = 0; s < 8; ++s) {
                if (vf[s] <= tau) {
                    int j = (l + 32 * i) * 8 + s;
                    int base = atomicAdd(&g_ccnt[grp], 1);
                    if (base < SCAP)
                        g_cand[grp * SCAP + base] = (unsigned short)((pl << 10) | j);
                }
            }
        }
    }
}

// ---------------------------------------------------------------------------
// K5: exact (FROZEN chain, k-ascending) recheck + fused quantize/loss/hist.
// Z tile transposed [pl][257] (conflict-free LDS); embed via float4 __ldg.
// grid 1024 x 256.
// ---------------------------------------------------------------------------
__global__ void vq_exact_q(const float* __restrict__ z,
                           const float* __restrict__ embed,
                           float* __restrict__ out) {
    extern __shared__ float Zt[];          // [pl 64][ZTS 257]
    __shared__ ull    key[64];
    __shared__ float  sA[64];
    __shared__ int    sidx[64];
    __shared__ double red[256];

    const int t  = threadIdx.x;
    const int tb = blockIdx.x;
    const int b  = tb >> 7;
    const int s0 = (tb & 127) * 64;
    const float* zb = z + (size_t)b * BATCH_STRIDE + s0;

#pragma unroll
    for (int i = 0; i < 16; ++i) {
        int lin = i * 256 + t;
        int k = lin >> 4, mq = lin & 15;
        float4 v = *(const float4*)(zb + (size_t)k * S_DIM + mq * 4);
        Zt[(mq * 4 + 0) * ZTS + k] = v.x;
        Zt[(mq * 4 + 1) * ZTS + k] = v.y;
        Zt[(mq * 4 + 2) * ZTS + k] = v.z;
        Zt[(mq * 4 + 3) * ZTS + k] = v.w;
    }
    if (t < 64) key[t] = ~0ull;
    __syncthreads();

    if (t < 64) {                          // FROZEN A chain (same values, k asc)
        float a = 0.f;
        const float* zr = Zt + t * ZTS;
#pragma unroll 8
        for (int k = 0; k < 256; ++k) a = fmaf(zr[k], zr[k], a);
        sA[t] = a;
    }
    __syncthreads();

    const int ncand = g_ccnt[tb];
    if (ncand <= SCAP) {
        for (int i = t; i < ncand; i += 256) {
            int e  = g_cand[tb * SCAP + i];
            int pl = e >> 10, j = e & 1023;
            const float*  zr  = Zt + pl * ZTS;
            const float4* er4 = (const float4*)(embed + (size_t)j * C_DIM);
            float m = 0.f;                 // FROZEN exact chain (k ascending)
#pragma unroll 8
            for (int k4 = 0; k4 < 64; ++k4) {
                float4 e4 = __ldg(&er4[k4]);
                m = fmaf(zr[4 * k4 + 0], e4.x, m);
                m = fmaf(zr[4 * k4 + 1], e4.y, m);
                m = fmaf(zr[4 * k4 + 2], e4.z, m);
                m = fmaf(zr[4 * k4 + 3], e4.w, m);
            }
            float d = __fadd_rn(__fadd_rn(sA[pl], g_e2[j]), -2.0f * m);
            atomicMin(&key[pl], ((ull)(unsigned)__float_as_int(d) << 32) | (unsigned)j);
        }
    } else {                               // overflow: deterministic full eval
        for (int i = t; i < 64 * 1024; i += 256) {
            int pl = i >> 10, j = i & 1023;
            const float*  zr  = Zt + pl * ZTS;
            const float4* er4 = (const float4*)(embed + (size_t)j * C_DIM);
            float m = 0.f;
#pragma unroll 8
            for (int k4 = 0; k4 < 64; ++k4) {
                float4 e4 = __ldg(&er4[k4]);
                m = fmaf(zr[4 * k4 + 0], e4.x, m);
                m = fmaf(zr[4 * k4 + 1], e4.y, m);
                m = fmaf(zr[4 * k4 + 2], e4.z, m);
                m = fmaf(zr[4 * k4 + 3], e4.w, m);
            }
            float d = __fadd_rn(__fadd_rn(sA[pl], g_e2[j]), -2.0f * m);
            atomicMin(&key[pl], ((ull)(unsigned)__float_as_int(d) << 32) | (unsigned)j);
        }
    }
    __syncthreads();

    if (t < 64) {
        int bi = (int)(key[t] & 0xFFFFFFFFull);
        sidx[t] = bi;
        out[IDX_OFF + tb * 64 + t] = (float)bi;
        atomicAdd(&g_cnt[bi], 1.0f);
    }
    __syncthreads();

    // fused quantize (FROZEN arithmetic), z read from Zt
    float* qb = out + ZQ_OFF + (size_t)b * BATCH_STRIDE + s0;
    double lacc = 0.0;
#pragma unroll
    for (int i = 0; i < 16; ++i) {
        int lin = i * 256 + t;
        int c = lin >> 4, mq = lin & 15;
        float4 zv;
        zv.x = Zt[(mq * 4 + 0) * ZTS + c];
        zv.y = Zt[(mq * 4 + 1) * ZTS + c];
        zv.z = Zt[(mq * 4 + 2) * ZTS + c];
        zv.w = Zt[(mq * 4 + 3) * ZTS + c];
        float4 ev;
        ev.x = __ldg(embed + (size_t)sidx[mq * 4 + 0] * C_DIM + c);
        ev.y = __ldg(embed + (size_t)sidx[mq * 4 + 1] * C_DIM + c);
        ev.z = __ldg(embed + (size_t)sidx[mq * 4 + 2] * C_DIM + c);
        ev.w = __ldg(embed + (size_t)sidx[mq * 4 + 3] * C_DIM + c);
        float dx = __fadd_rn(ev.x, -zv.x);
        float dy = __fadd_rn(ev.y, -zv.y);
        float dz = __fadd_rn(ev.z, -zv.z);
        float dw = __fadd_rn(ev.w, -zv.w);
        float4 qv;
        qv.x = __fadd_rn(zv.x, dx);
        qv.y = __fadd_rn(zv.y, dy);
        qv.z = __fadd_rn(zv.z, dz);
        qv.w = __fadd_rn(zv.w, dw);
        *(float4*)(qb + (size_t)c * S_DIM + mq * 4) = qv;
        lacc += (double)(dx * dx) + (double)(dy * dy)
              + (double)(dz * dz) + (double)(dw * dw);
    }

    red[t] = lacc;
    __syncthreads();
    for (int off = 128; off > 0; off >>= 1) {
        if (t < off) red[t] += red[t + off];
        __syncthreads();
    }
    if (t == 0) atomicAdd(&g_loss, red[0]);
}

// ---------------------------------------------------------------------------
// K6: finalize loss + perplexity.
// ---------------------------------------------------------------------------
__global__ void vq_finalize_kernel(float* __restrict__ out) {
    __shared__ float sred[1024];
    int t = threadIdx.x;
    float p = g_cnt[t] * (1.0f / (float)N_PTS);
    sred[t] = p * logf(p + 1e-10f);
    __syncthreads();
    for (int off = 512; off > 0; off >>= 1) {
        if (t < off) sred[t] += sred[t + off];
        __syncthreads();
    }
    if (t == 0) {
        out[PERP_OFF] = expf(-sred[0]);
        out[LOSS_OFF] = 0.25f * (float)(g_loss / (double)Z_ELEMS);
    }
}

// ---------------------------------------------------------------------------
extern "C" void kernel_launch(void* const* d_in, const int* in_sizes, int n_in,
                              void* d_out, int out_size) {
    const float* z     = (const float*)d_in[0];
    const float* embed = (const float*)d_in[1];
    float* out = (float*)d_out;

    cudaFuncSetAttribute(vq_gemm_h,  cudaFuncAttributeMaxDynamicSharedMemorySize, GEMM_SMEM);
    cudaFuncSetAttribute(vq_prep_z,  cudaFuncAttributeMaxDynamicSharedMemorySize, PREPZ_SMEM);
    cudaFuncSetAttribute(vq_exact_q, cudaFuncAttributeMaxDynamicSharedMemorySize, EXACT_SMEM);

    vq_prep_e<<<128, 256>>>(embed);
    vq_transpose_e<<<128, 256>>>(embed);
    vq_prep_z<<<1024, 256, PREPZ_SMEM>>>(z);
    vq_gemm_h<<<dim3(512, 16), 256, GEMM_SMEM>>>();
    vq_scan<<<8192, 256>>>();
    vq_exact_q<<<1024, 256, EXACT_SMEM>>>(z, embed, out);
    vq_finalize_kernel<<<1, 1024>>>(out);
}